// round 3
// baseline (speedup 1.0000x reference)
#include <cuda_runtime.h>
#include <cstdint>

// QPChargeNormalization, TMA-pipelined persistent kernel.
// Per row b (B=4096): n=8192, c=[c_iso|c_aniso], q=[int_iso|int_aniso]
//   h = (sum(charge[b]) - q.c) / (q.q),  x = c + h*q
// Output = [sol_iso (B*4096) | sol_aniso (B*4096)]
//
// grid = 148 persistent CTAs (1/SM), 512 threads. 3-stage smem pipeline
// filled by cp.async.bulk so DRAM reads continue during the per-row
// reduction (the bubble that capped R1 at 81% DRAM).

#define NT      512
#define NSTAGE  3
#define GRID    148

#define HALF        4096                    // floats per iso/aniso half-row
#define NCH         256                     // charge entries per row
#define HALF_BYTES  (HALF * 4)              // 16384
#define CH_BYTES    (NCH * 4)               // 1024
#define STAGE_FLOATS (4 * HALF + NCH)       // 16640
#define STAGE_BYTES  (STAGE_FLOATS * 4)     // 66560
#define SMEM_STAGE0  128                    // stages start 128B-aligned
#define SMEM_TOTAL   (SMEM_STAGE0 + NSTAGE * STAGE_BYTES)   // 199808

__device__ __forceinline__ uint32_t smem_u32(const void* p) {
    return (uint32_t)__cvta_generic_to_shared(p);
}

__device__ __forceinline__ void mbar_init(uint32_t mbar, uint32_t cnt) {
    asm volatile("mbarrier.init.shared::cta.b64 [%0], %1;" :: "r"(mbar), "r"(cnt) : "memory");
}

__device__ __forceinline__ void mbar_expect_tx(uint32_t mbar, uint32_t bytes) {
    asm volatile("mbarrier.arrive.expect_tx.shared::cta.b64 _, [%0], %1;"
                 :: "r"(mbar), "r"(bytes) : "memory");
}

__device__ __forceinline__ void mbar_wait(uint32_t mbar, uint32_t parity) {
    uint32_t done;
    asm volatile(
        "{\n\t.reg .pred p;\n\t"
        "mbarrier.try_wait.parity.acquire.cta.shared::cta.b64 p, [%1], %2;\n\t"
        "selp.b32 %0, 1, 0, p;\n\t}"
        : "=r"(done) : "r"(mbar), "r"(parity) : "memory");
    if (!done) {
        asm volatile(
            "{\n\t.reg .pred P1;\n\t"
            "W_%=:\n\t"
            "mbarrier.try_wait.parity.acquire.cta.shared::cta.b64 P1, [%0], %1, 0x989680;\n\t"
            "@P1 bra.uni D_%=;\n\t"
            "bra.uni W_%=;\n\t"
            "D_%=:\n\t}"
            :: "r"(mbar), "r"(parity) : "memory");
    }
}

__device__ __forceinline__ void bulk_ld(uint32_t dst_smem, const void* src,
                                        uint32_t bytes, uint32_t mbar) {
    asm volatile(
        "cp.async.bulk.shared::cta.global.mbarrier::complete_tx::bytes [%0], [%1], %2, [%3];"
        :: "r"(dst_smem), "l"(src), "r"(bytes), "r"(mbar) : "memory");
}

__device__ __forceinline__ float dot4(float4 a, float4 b) {
    return fmaf(a.x, b.x, fmaf(a.y, b.y, fmaf(a.z, b.z, a.w * b.w)));
}

__device__ __forceinline__ float4 axpy4(float h, float4 q, float4 c) {
    float4 o;
    o.x = fmaf(h, q.x, c.x);
    o.y = fmaf(h, q.y, c.y);
    o.z = fmaf(h, q.z, c.z);
    o.w = fmaf(h, q.w, c.w);
    return o;
}

__global__ void __launch_bounds__(NT, 1)
qp_tma_kernel(const float* __restrict__ c_iso,
              const float* __restrict__ c_aniso,
              const float* __restrict__ q_iso,
              const float* __restrict__ q_aniso,
              const float* __restrict__ charge,
              float4*      __restrict__ out,
              int B)
{
    extern __shared__ char smem[];
    const int tid = threadIdx.x;
    const int bid = blockIdx.x;

    // mbarriers live at smem[0..24), stages at smem + 128
    uint32_t mbar0 = smem_u32(smem);
    float*   stg0  = (float*)(smem + SMEM_STAGE0);

    // rows handled by this CTA: r = bid + j*GRID
    int nloc = (B > bid) ? (B - bid + GRID - 1) / GRID : 0;

    if (tid == 0) {
        #pragma unroll
        for (int s = 0; s < NSTAGE; s++) mbar_init(mbar0 + 8u * s, 1);
        asm volatile("fence.proxy.async.shared::cta;" ::: "memory");
    }
    __syncthreads();

    // ---- issue helper (tid 0 only) ----
    auto issue = [&](int j) {
        int r = bid + j * GRID;
        int s = j % NSTAGE;
        uint32_t mb  = mbar0 + 8u * s;
        uint32_t dst = smem_u32(stg0 + (size_t)s * STAGE_FLOATS);
        mbar_expect_tx(mb, STAGE_BYTES);
        bulk_ld(dst,                  c_iso   + (size_t)r * HALF, HALF_BYTES, mb);
        bulk_ld(dst + 1 * HALF_BYTES, c_aniso + (size_t)r * HALF, HALF_BYTES, mb);
        bulk_ld(dst + 2 * HALF_BYTES, q_iso   + (size_t)r * HALF, HALF_BYTES, mb);
        bulk_ld(dst + 3 * HALF_BYTES, q_aniso + (size_t)r * HALF, HALF_BYTES, mb);
        bulk_ld(dst + 4 * HALF_BYTES, charge  + (size_t)r * NCH,  CH_BYTES,   mb);
    };

    if (tid == 0) {
        int pre = nloc < NSTAGE ? nloc : NSTAGE;
        for (int j = 0; j < pre; j++) issue(j);
    }

    __shared__ float s_qc[16], s_qq[16], s_Q[16];
    __shared__ float s_h;
    const int wid  = tid >> 5;
    const int lane = tid & 31;

    for (int j = 0; j < nloc; j++) {
        const int s  = j % NSTAGE;
        const int ph = (j / NSTAGE) & 1;
        mbar_wait(mbar0 + 8u * s, ph);

        const float*  st = stg0 + (size_t)s * STAGE_FLOATS;
        const float4* sc = (const float4*)st;

        // layout (float4 units): ci[0..1024) ca[1024..2048) qi[2048..3072) qa[3072..4096)
        float4 c0 = sc[tid];
        float4 c1 = sc[tid + NT];
        float4 c2 = sc[1024 + tid];
        float4 c3 = sc[1024 + tid + NT];
        float4 q0 = sc[2048 + tid];
        float4 q1 = sc[2048 + tid + NT];
        float4 q2 = sc[3072 + tid];
        float4 q3 = sc[3072 + tid + NT];
        float  Qv = (tid < NCH) ? st[4 * HALF + tid] : 0.0f;

        float qc = dot4(q0, c0) + dot4(q1, c1) + dot4(q2, c2) + dot4(q3, c3);
        float qq = dot4(q0, q0) + dot4(q1, q1) + dot4(q2, q2) + dot4(q3, q3);

        #pragma unroll
        for (int m = 16; m; m >>= 1) {
            qc += __shfl_xor_sync(0xffffffffu, qc, m);
            qq += __shfl_xor_sync(0xffffffffu, qq, m);
            Qv += __shfl_xor_sync(0xffffffffu, Qv, m);
        }
        if (lane == 0) { s_qc[wid] = qc; s_qq[wid] = qq; s_Q[wid] = Qv; }
        __syncthreads();
        // All threads have consumed stage s into registers -> refill it now,
        // overlapping TMA with the rest of the reduction + stores.
        if (tid == 0) {
            int jn = j + NSTAGE;
            if (jn < nloc) issue(jn);
        }
        if (wid == 0) {
            float a  = (lane < 16) ? s_qc[lane] : 0.0f;
            float g  = (lane < 16) ? s_qq[lane] : 0.0f;
            float qs = (lane < 16) ? s_Q[lane]  : 0.0f;
            #pragma unroll
            for (int m = 8; m; m >>= 1) {
                a  += __shfl_xor_sync(0xffffffffu, a,  m);
                g  += __shfl_xor_sync(0xffffffffu, g,  m);
                qs += __shfl_xor_sync(0xffffffffu, qs, m);
            }
            if (lane == 0) s_h = (qs - a) / g;
        }
        __syncthreads();
        const float h = s_h;

        const int r = bid + j * GRID;
        float4* oi = out + (size_t)r * 1024;
        float4* oa = out + (size_t)B * 1024 + (size_t)r * 1024;
        oi[tid]      = axpy4(h, q0, c0);
        oi[tid + NT] = axpy4(h, q1, c1);
        oa[tid]      = axpy4(h, q2, c2);
        oa[tid + NT] = axpy4(h, q3, c3);
        // no trailing barrier needed: next iteration's wait/sync provides ordering
    }
}

extern "C" void kernel_launch(void* const* d_in, const int* in_sizes, int n_in,
                              void* d_out, int out_size)
{
    const float* c_iso   = (const float*)d_in[0];
    const float* c_aniso = (const float*)d_in[1];
    const float* q_iso   = (const float*)d_in[2];
    const float* q_aniso = (const float*)d_in[3];
    const float* charge  = (const float*)d_in[4];
    float4*      out     = (float4*)d_out;

    const int B = in_sizes[4] / NCH;   // charge is [B, 256]

    static bool attr_done = false;     // idempotent attribute set (not a work guard)
    if (!attr_done) {
        cudaFuncSetAttribute(qp_tma_kernel,
                             cudaFuncAttributeMaxDynamicSharedMemorySize, SMEM_TOTAL);
        attr_done = true;
    }

    qp_tma_kernel<<<GRID, NT, SMEM_TOTAL>>>(c_iso, c_aniso, q_iso, q_aniso,
                                            charge, out, B);
}

// round 4
// speedup vs baseline: 1.2185x; 1.2185x over previous
#include <cuda_runtime.h>
#include <cstdint>

// QPChargeNormalization — persistent work-stealing, register-resident.
// Per row b (B=4096): n=8192, c=[c_iso|c_aniso], q=[int_iso|int_aniso]
//   h = (sum(charge[b]) - q.c) / (q.q),  x = c + h*q
// Output = [sol_iso (B*4096) | sol_aniso (B*4096)]
//
// grid = 296 (2 CTAs/SM, register-limited), 512 threads. Rows claimed via a
// global atomic ticket; the next ticket is fetched while the current row's
// LDGs are in flight. Single-barrier reduction keeps the memory bubble short.

#define NT    512
#define GRID  296
#define HALF  4096
#define NCH   256

__device__ int g_row_ctr;

__global__ void qp_init_ctr() { g_row_ctr = GRID; }

__device__ __forceinline__ float dot4(float4 a, float4 b) {
    return fmaf(a.x, b.x, fmaf(a.y, b.y, fmaf(a.z, b.z, a.w * b.w)));
}

__device__ __forceinline__ float4 axpy4(float h, float4 q, float4 c) {
    float4 o;
    o.x = fmaf(h, q.x, c.x);
    o.y = fmaf(h, q.y, c.y);
    o.z = fmaf(h, q.z, c.z);
    o.w = fmaf(h, q.w, c.w);
    return o;
}

__global__ void __launch_bounds__(NT)
qp_persistent_kernel(const float4* __restrict__ c_iso,
                     const float4* __restrict__ c_aniso,
                     const float4* __restrict__ q_iso,
                     const float4* __restrict__ q_aniso,
                     const float*  __restrict__ charge,
                     float4*       __restrict__ out,
                     int B)
{
    const int tid  = threadIdx.x;
    const int wid  = tid >> 5;
    const int lane = tid & 31;

    __shared__ int   s_next[2];
    __shared__ float s_p[48];          // [0..16) qc, [16..32) qq, [32..48) Q

    int r = blockIdx.x;                // first row is pre-assigned
    int parity = 0;

    while (r < B) {
        const size_t row4 = (size_t)r * 1024;

        // 8 streaming float4 loads straight into registers (front-batched).
        float4 c0 = __ldcs(c_iso   + row4 + tid);
        float4 c1 = __ldcs(c_iso   + row4 + tid + NT);
        float4 c2 = __ldcs(c_aniso + row4 + tid);
        float4 c3 = __ldcs(c_aniso + row4 + tid + NT);
        float4 q0 = __ldcs(q_iso   + row4 + tid);
        float4 q1 = __ldcs(q_iso   + row4 + tid + NT);
        float4 q2 = __ldcs(q_aniso + row4 + tid);
        float4 q3 = __ldcs(q_aniso + row4 + tid + NT);
        float  Qv = (tid < NCH) ? __ldcs(charge + (size_t)r * NCH + tid) : 0.0f;

        // Claim the next row while the loads above are in flight
        // (ATOMG ~318 cyc hides under the LDG wait).
        if (tid == 0) s_next[parity] = atomicAdd(&g_row_ctr, 1);

        float qc = dot4(q0, c0) + dot4(q1, c1) + dot4(q2, c2) + dot4(q3, c3);
        float qq = dot4(q0, q0) + dot4(q1, q1) + dot4(q2, q2) + dot4(q3, q3);

        #pragma unroll
        for (int m = 16; m; m >>= 1) {
            qc += __shfl_xor_sync(0xffffffffu, qc, m);
            qq += __shfl_xor_sync(0xffffffffu, qq, m);
            Qv += __shfl_xor_sync(0xffffffffu, Qv, m);
        }
        if (lane == 0) { s_p[wid] = qc; s_p[16 + wid] = qq; s_p[32 + wid] = Qv; }
        __syncthreads();   // the ONLY barrier per row

        // Every warp redundantly reduces the 16 partials — no second barrier.
        float a  = (lane < 16) ? s_p[lane]      : 0.0f;
        float g  = (lane < 16) ? s_p[16 + lane] : 0.0f;
        float qs = (lane < 16) ? s_p[32 + lane] : 0.0f;
        #pragma unroll
        for (int m = 8; m; m >>= 1) {
            a  += __shfl_xor_sync(0xffffffffu, a,  m);
            g  += __shfl_xor_sync(0xffffffffu, g,  m);
            qs += __shfl_xor_sync(0xffffffffu, qs, m);
        }
        const float h = __shfl_sync(0xffffffffu, (qs - a) / g, 0);

        float4* oi = out + row4;                        // iso block
        float4* oa = out + (size_t)B * 1024 + row4;     // aniso block
        __stcs(oi + tid,      axpy4(h, q0, c0));
        __stcs(oi + tid + NT, axpy4(h, q1, c1));
        __stcs(oa + tid,      axpy4(h, q2, c2));
        __stcs(oa + tid + NT, axpy4(h, q3, c3));

        r = s_next[parity];   // written pre-barrier, read post-barrier: safe
        parity ^= 1;          // double-buffered so next tid0 write can't race
    }
}

extern "C" void kernel_launch(void* const* d_in, const int* in_sizes, int n_in,
                              void* d_out, int out_size)
{
    const float4* c_iso   = (const float4*)d_in[0];
    const float4* c_aniso = (const float4*)d_in[1];
    const float4* q_iso   = (const float4*)d_in[2];
    const float4* q_aniso = (const float4*)d_in[3];
    const float*  charge  = (const float*) d_in[4];
    float4*       out     = (float4*)d_out;

    const int B = in_sizes[4] / NCH;   // charge is [B, 256]

    qp_init_ctr<<<1, 1>>>();
    qp_persistent_kernel<<<GRID, NT>>>(c_iso, c_aniso, q_iso, q_aniso,
                                       charge, out, B);
}